// round 6
// baseline (speedup 1.0000x reference)
#include <cuda_runtime.h>
#include <cstdint>

#define N_NODES 100000
#define N_EDGES 1600000
#define NF 100
#define NH 32

typedef unsigned long long u64;

// ---------------- device scratch (no allocations allowed) ----------------
__device__ int   g_is64;
__device__ int   g_cursor;
__device__ int   g_deg    [N_NODES];
__device__ int   g_off    [N_NODES];
__device__ int   g_fillpos[N_NODES];
__device__ float g_dinv   [N_NODES];
__device__ int   g_src    [N_EDGES];
__device__ int   g_dstv   [N_EDGES];
__device__ int   g_csr    [N_EDGES];       // src per CSR slot (grouped by dst)
__device__ float g_h      [N_NODES * NH];  // h' = (x @ W1) * dinv[row]
__device__ float g_g      [N_NODES * 2];   // g' = (dropout(relu(.+b1)) @ W2) * dinv[row]

// ---------------- helpers ----------------
__device__ __forceinline__ int ld_idx(const void* ei, long long pos, int is64) {
    if (is64) return (int)((const long long*)ei)[pos];
    return ((const int*)ei)[pos];
}

// JAX threefry2x32, key = (0, 42)  [jax.random.key(42)], 20 rounds
__device__ __forceinline__ uint2 threefry_0_42(unsigned x0, unsigned x1) {
    const unsigned ks0 = 0u, ks1 = 42u, ks2 = 0x1BD11BDAu ^ 42u;
    x0 += ks0; x1 += ks1;
#define TFR(r) { x0 += x1; x1 = ((x1 << (r)) | (x1 >> (32 - (r)))) ^ x0; }
    TFR(13) TFR(15) TFR(26) TFR(6)
    x0 += ks1; x1 += ks2 + 1u;
    TFR(17) TFR(29) TFR(16) TFR(24)
    x0 += ks2; x1 += ks0 + 2u;
    TFR(13) TFR(15) TFR(26) TFR(6)
    x0 += ks0; x1 += ks1 + 3u;
    TFR(17) TFR(29) TFR(16) TFR(24)
    x0 += ks1; x1 += ks2 + 4u;
    TFR(13) TFR(15) TFR(26) TFR(6)
    x0 += ks2; x1 += ks0 + 5u;
#undef TFR
    return make_uint2(x0, x1);
}

// Partitionable threefry bits for flat idx: counter (0, idx), out0 ^ out1.
__device__ __forceinline__ unsigned rng_bits_partitionable(unsigned idx) {
    uint2 o = threefry_0_42(0u, idx);
    return o.x ^ o.y;
}

// ---------------- kernels ----------------

// Zero deg + cursor; block 0 detects int64 vs int32 edge_index
// (int64 ids < 2^31 -> all odd 32-bit words zero).
__global__ __launch_bounds__(256) void k_init(const unsigned* ei) {
    int i = blockIdx.x * 256 + threadIdx.x;
    if (i < N_NODES) g_deg[i] = 0;
    if (blockIdx.x == 0) {
        __shared__ int s_any;
        if (threadIdx.x == 0) { s_any = 0; g_cursor = 0; }
        __syncthreads();
        int any = 0;
        for (int k = threadIdx.x; k < 1024; k += 256)
            if (ei[2 * k + 1] != 0u) any = 1;
        if (any) atomicOr(&s_any, 1);
        __syncthreads();
        if (threadIdx.x == 0) g_is64 = s_any ? 0 : 1;
    }
}

// Per edge: count in-degree and convert indices to int32.
__global__ __launch_bounds__(256) void k_deg(const void* ei) {
    int e = blockIdx.x * 256 + threadIdx.x;
    if (e >= N_EDGES) return;
    int is64 = g_is64;
    int s = ld_idx(ei, e, is64);
    int d = ld_idx(ei, (long long)N_EDGES + e, is64);
    g_src[e] = s;
    g_dstv[e] = d;
    atomicAdd(&g_deg[d], 1);
}

// Prologue: per-block scan of deg -> CSR offsets (order-free via global cursor),
// dinv = rsqrt(deg+1), fillpos = off. Body: h' = (x @ W1) * dinv.
// Block: 256 threads = 256 rows x 32 cols. Thread: 4 rows x 8 cols.
__global__ __launch_bounds__(256) void k_gemm1(const float* __restrict__ x,
                                               const float* __restrict__ W1) {
    __shared__ float Ws[NF * NH];      // 100x32
    __shared__ float xs[20 * 264];     // k-chunk of x, transposed, padded
    __shared__ int   s_scan[256];
    __shared__ int   s_base;
    const int tid  = threadIdx.x;
    const int row0 = blockIdx.x * 256;
    const int rg = tid >> 2;           // 0..63 -> rows rg*4..rg*4+3
    const int cg = tid & 3;            // 0..3  -> cols cg*8..cg*8+7

    // ---- offsets + dinv prologue ----
    {
        int gr = row0 + tid;
        int mydeg = (gr < N_NODES) ? g_deg[gr] : 0;
        if (gr < N_NODES) g_dinv[gr] = rsqrtf((float)(mydeg + 1));
        s_scan[tid] = mydeg;
        __syncthreads();
#pragma unroll
        for (int off = 1; off < 256; off <<= 1) {
            int v = (tid >= off) ? s_scan[tid - off] : 0;
            __syncthreads();
            s_scan[tid] += v;
            __syncthreads();
        }
        if (tid == 255) s_base = atomicAdd(&g_cursor, s_scan[255]);
        __syncthreads();
        if (gr < N_NODES) {
            int my_off = s_base + s_scan[tid] - mydeg;
            g_off[gr] = my_off;
            g_fillpos[gr] = my_off;
        }
    }

    for (int i = tid; i < NF * NH; i += 256) Ws[i] = W1[i];

    u64 acc[4][4];
#pragma unroll
    for (int i = 0; i < 4; i++)
#pragma unroll
        for (int j = 0; j < 4; j++) acc[i][j] = 0ull;

    for (int kc = 0; kc < 5; kc++) {
        __syncthreads();
        {
            int gr = row0 + tid;
            if (gr >= N_NODES) gr = N_NODES - 1;
            const float4* xp = (const float4*)(x + (size_t)gr * NF + kc * 20);
#pragma unroll
            for (int q = 0; q < 5; q++) {
                float4 v = __ldg(xp + q);
                xs[(q * 4 + 0) * 264 + tid] = v.x;
                xs[(q * 4 + 1) * 264 + tid] = v.y;
                xs[(q * 4 + 2) * 264 + tid] = v.z;
                xs[(q * 4 + 3) * 264 + tid] = v.w;
            }
        }
        __syncthreads();
#pragma unroll
        for (int kk = 0; kk < 20; kk++) {
            float4 xv = *(const float4*)&xs[kk * 264 + rg * 4];
            const u64* wp = (const u64*)&Ws[(kc * 20 + kk) * NH + cg * 8];
            u64 w0 = wp[0], w1 = wp[1], w2 = wp[2], w3 = wp[3];
            u64 xd0, xd1, xd2, xd3;
            asm("mov.b64 %0,{%1,%1};" : "=l"(xd0) : "r"(__float_as_uint(xv.x)));
            asm("mov.b64 %0,{%1,%1};" : "=l"(xd1) : "r"(__float_as_uint(xv.y)));
            asm("mov.b64 %0,{%1,%1};" : "=l"(xd2) : "r"(__float_as_uint(xv.z)));
            asm("mov.b64 %0,{%1,%1};" : "=l"(xd3) : "r"(__float_as_uint(xv.w)));
#define FMA2(a, b, c) asm("fma.rn.f32x2 %0,%1,%2,%0;" : "+l"(a) : "l"(b), "l"(c))
            FMA2(acc[0][0], xd0, w0); FMA2(acc[0][1], xd0, w1);
            FMA2(acc[0][2], xd0, w2); FMA2(acc[0][3], xd0, w3);
            FMA2(acc[1][0], xd1, w0); FMA2(acc[1][1], xd1, w1);
            FMA2(acc[1][2], xd1, w2); FMA2(acc[1][3], xd1, w3);
            FMA2(acc[2][0], xd2, w0); FMA2(acc[2][1], xd2, w1);
            FMA2(acc[2][2], xd2, w2); FMA2(acc[2][3], xd2, w3);
            FMA2(acc[3][0], xd3, w0); FMA2(acc[3][1], xd3, w1);
            FMA2(acc[3][2], xd3, w2); FMA2(acc[3][3], xd3, w3);
#undef FMA2
        }
    }

    // h' = h * dinv[row]  (dinv for in-block rows written in prologue)
#pragma unroll
    for (int ri = 0; ri < 4; ri++) {
        int gr = row0 + rg * 4 + ri;
        if (gr < N_NODES) {
            float di = g_dinv[gr];
            float2 p0 = *(float2*)&acc[ri][0];
            float2 p1 = *(float2*)&acc[ri][1];
            float2 p2 = *(float2*)&acc[ri][2];
            float2 p3 = *(float2*)&acc[ri][3];
            float* hp = g_h + (size_t)gr * NH + cg * 8;
            *(float4*)(hp)     = make_float4(p0.x * di, p0.y * di, p1.x * di, p1.y * di);
            *(float4*)(hp + 4) = make_float4(p2.x * di, p2.y * di, p3.x * di, p3.y * di);
        }
    }
}

// Scatter src into CSR slots. Slot via atomic cursor per dst (fillpos=off seed).
__global__ __launch_bounds__(256) void k_fill() {
    int e = blockIdx.x * 256 + threadIdx.x;
    if (e >= N_EDGES) return;
    int s = g_src[e];
    int d = g_dstv[e];
    int slot = atomicAdd(&g_fillpos[d], 1);
    g_csr[slot] = s;
}

// Layer-1 aggregation (gather, warp per node) fused with bias+relu+dropout+W2.
// h is premultiplied by dinv[src]; final scale by dinv[node].
__global__ __launch_bounds__(512) void k_agg1(const float* __restrict__ b1,
                                              const float* __restrict__ W2) {
    int node = (blockIdx.x * 512 + threadIdx.x) >> 5;
    int lane = threadIdx.x & 31;
    if (node >= N_NODES) return;

    int off = g_off[node];
    int len = g_deg[node];
    float di = __ldg(&g_dinv[node]);
    float acc = 0.f;
    for (int base = 0; base < len; base += 32) {
        int k = base + lane;
        int sl = (k < len) ? __ldg(&g_csr[off + k]) : 0;
        int cnt = min(32, len - base);
#pragma unroll 4
        for (int j = 0; j < cnt; j++) {
            int s = __shfl_sync(0xffffffffu, sl, j);
            acc += __ldg(&g_h[(size_t)s * NH + lane]);
        }
    }
    // self loop + neighbor sum share the dinv[node] factor
    acc += g_h[(size_t)node * NH + lane];
    acc *= di;

    // bias + relu + dropout
    float v = acc + __ldg(&b1[lane]);
    v = fmaxf(v, 0.f);
    unsigned bits = rng_bits_partitionable((unsigned)(node * 32 + lane));
    v = ((bits >> 9) < 6710887u) ? v * 1.25f : 0.f;

    // @ W2, warp reduce; store g' = g * dinv[node]
    float p0 = v * __ldg(&W2[lane * 2 + 0]);
    float p1 = v * __ldg(&W2[lane * 2 + 1]);
#pragma unroll
    for (int o = 16; o; o >>= 1) {
        p0 += __shfl_xor_sync(0xffffffffu, p0, o);
        p1 += __shfl_xor_sync(0xffffffffu, p1, o);
    }
    if (lane == 0) {
        g_g[node * 2 + 0] = p0 * di;
        g_g[node * 2 + 1] = p1 * di;
    }
}

// Layer-2 aggregation (gather, warp per node) fused with b2 + log_softmax.
// g is premultiplied by dinv[src]; final scale by dinv[node].
__global__ __launch_bounds__(512) void k_agg2(const float* __restrict__ b2,
                                              float* __restrict__ out) {
    int node = (blockIdx.x * 512 + threadIdx.x) >> 5;
    int lane = threadIdx.x & 31;
    if (node >= N_NODES) return;

    int off = g_off[node];
    int len = g_deg[node];
    float di = __ldg(&g_dinv[node]);
    float a0 = 0.f, a1 = 0.f;
    for (int k = lane; k < len; k += 32) {
        int s = __ldg(&g_csr[off + k]);
        float2 gv = *(const float2*)(g_g + (size_t)s * 2);
        a0 += gv.x;
        a1 += gv.y;
    }
#pragma unroll
    for (int o = 16; o; o >>= 1) {
        a0 += __shfl_xor_sync(0xffffffffu, a0, o);
        a1 += __shfl_xor_sync(0xffffffffu, a1, o);
    }
    if (lane == 0) {
        float la = (a0 + g_g[node * 2 + 0]) * di + __ldg(&b2[0]);
        float lb = (a1 + g_g[node * 2 + 1]) * di + __ldg(&b2[1]);
        float m = fmaxf(la, lb);
        float lse = m + logf(expf(la - m) + expf(lb - m));
        *(float2*)(out + (size_t)node * 2) = make_float2(la - lse, lb - lse);
    }
}

// ---------------- launch ----------------
extern "C" void kernel_launch(void* const* d_in, const int* in_sizes, int n_in,
                              void* d_out, int out_size) {
    const float* x  = (const float*)d_in[0];
    const void*  ei = d_in[1];
    const float* W1 = (const float*)d_in[2];
    const float* b1 = (const float*)d_in[3];
    const float* W2 = (const float*)d_in[4];
    const float* b2 = (const float*)d_in[5];
    float* out = (float*)d_out;

    k_init<<<(N_NODES + 255) / 256, 256>>>((const unsigned*)ei);
    k_deg<<<(N_EDGES + 255) / 256, 256>>>(ei);
    k_gemm1<<<(N_NODES + 255) / 256, 256>>>(x, W1);
    k_fill<<<(N_EDGES + 255) / 256, 256>>>();
    k_agg1<<<(int)(((long long)N_NODES * 32 + 511) / 512), 512>>>(b1, W2);
    k_agg2<<<(int)(((long long)N_NODES * 32 + 511) / 512), 512>>>(b2, out);
}

// round 7
// speedup vs baseline: 1.1657x; 1.1657x over previous
#include <cuda_runtime.h>
#include <cstdint>

#define N_NODES 100000
#define N_EDGES 1600000
#define NF 100
#define NH 32

typedef unsigned long long u64;

// ---------------- device scratch (no allocations allowed) ----------------
// g_deg and g_cursor are zero at module load; k_agg2 re-zeroes them at the end
// of every call so each graph replay starts from the same state.
__device__ int   g_cursor;
__device__ int   g_deg    [N_NODES];
__device__ int   g_off    [N_NODES];
__device__ int   g_fillpos[N_NODES];
__device__ float g_dinv   [N_NODES];
__device__ int   g_csr    [N_EDGES];       // src per CSR slot (grouped by dst)
__device__ float g_h      [N_NODES * NH];  // h' = (x @ W1) * dinv[row]
__device__ float g_g      [N_NODES * 2];   // g' = (dropout(relu(.+b1)) @ W2) * dinv[row]

// ---------------- helpers ----------------
// Block-local int64-vs-int32 detection: for int64 ids < 2^31 every odd 32-bit
// word of the src half is zero; for int32 those words are random node ids.
// Scans the first 256 odd words (L2-hot, shared by all blocks).
__device__ __forceinline__ int detect_is64(const unsigned* ei) {
    int any = (ei[2 * threadIdx.x + 1] != 0u) ? 1 : 0;
    return __syncthreads_or(any) ? 0 : 1;
}

// JAX threefry2x32, key = (0, 42)  [jax.random.key(42)], 20 rounds
__device__ __forceinline__ uint2 threefry_0_42(unsigned x0, unsigned x1) {
    const unsigned ks0 = 0u, ks1 = 42u, ks2 = 0x1BD11BDAu ^ 42u;
    x0 += ks0; x1 += ks1;
#define TFR(r) { x0 += x1; x1 = ((x1 << (r)) | (x1 >> (32 - (r)))) ^ x0; }
    TFR(13) TFR(15) TFR(26) TFR(6)
    x0 += ks1; x1 += ks2 + 1u;
    TFR(17) TFR(29) TFR(16) TFR(24)
    x0 += ks2; x1 += ks0 + 2u;
    TFR(13) TFR(15) TFR(26) TFR(6)
    x0 += ks0; x1 += ks1 + 3u;
    TFR(17) TFR(29) TFR(16) TFR(24)
    x0 += ks1; x1 += ks2 + 4u;
    TFR(13) TFR(15) TFR(26) TFR(6)
    x0 += ks2; x1 += ks0 + 5u;
#undef TFR
    return make_uint2(x0, x1);
}

// Partitionable threefry bits for flat idx: counter (0, idx), out0 ^ out1.
__device__ __forceinline__ unsigned rng_bits_partitionable(unsigned idx) {
    uint2 o = threefry_0_42(0u, idx);
    return o.x ^ o.y;
}

// ---------------- kernels ----------------

// Per edge: count in-degree (reads ONLY the dst half of edge_index).
__global__ __launch_bounds__(256) void k_deg(const unsigned* ei) {
    int is64 = detect_is64(ei);
    int e = blockIdx.x * 256 + threadIdx.x;
    if (e >= N_EDGES) return;
    int d = is64 ? (int)((const long long*)ei)[(long long)N_EDGES + e]
                 : ((const int*)ei)[N_EDGES + e];
    atomicAdd(&g_deg[d], 1);
}

// Prologue: per-block scan of deg -> CSR offsets (order-free via global cursor),
// dinv = rsqrt(deg+1), fillpos = off. Body: h' = (x @ W1) * dinv.
// Block: 256 threads = 256 rows x 32 cols. Thread: 4 rows x 8 cols.
__global__ __launch_bounds__(256) void k_gemm1(const float* __restrict__ x,
                                               const float* __restrict__ W1) {
    __shared__ float Ws[NF * NH];      // 100x32
    __shared__ float xs[20 * 264];     // k-chunk of x, transposed, padded
    __shared__ int   s_scan[256];
    __shared__ int   s_base;
    const int tid  = threadIdx.x;
    const int row0 = blockIdx.x * 256;
    const int rg = tid >> 2;           // 0..63 -> rows rg*4..rg*4+3
    const int cg = tid & 3;            // 0..3  -> cols cg*8..cg*8+7

    // ---- offsets + dinv prologue ----
    {
        int gr = row0 + tid;
        int mydeg = (gr < N_NODES) ? g_deg[gr] : 0;
        if (gr < N_NODES) g_dinv[gr] = rsqrtf((float)(mydeg + 1));
        s_scan[tid] = mydeg;
        __syncthreads();
#pragma unroll
        for (int off = 1; off < 256; off <<= 1) {
            int v = (tid >= off) ? s_scan[tid - off] : 0;
            __syncthreads();
            s_scan[tid] += v;
            __syncthreads();
        }
        if (tid == 255) s_base = atomicAdd(&g_cursor, s_scan[255]);
        __syncthreads();
        if (gr < N_NODES) {
            int my_off = s_base + s_scan[tid] - mydeg;
            g_off[gr] = my_off;
            g_fillpos[gr] = my_off;
        }
    }

    for (int i = tid; i < NF * NH; i += 256) Ws[i] = W1[i];

    u64 acc[4][4];
#pragma unroll
    for (int i = 0; i < 4; i++)
#pragma unroll
        for (int j = 0; j < 4; j++) acc[i][j] = 0ull;

    for (int kc = 0; kc < 5; kc++) {
        __syncthreads();
        {
            int gr = row0 + tid;
            if (gr >= N_NODES) gr = N_NODES - 1;
            const float4* xp = (const float4*)(x + (size_t)gr * NF + kc * 20);
#pragma unroll
            for (int q = 0; q < 5; q++) {
                float4 v = __ldg(xp + q);
                xs[(q * 4 + 0) * 264 + tid] = v.x;
                xs[(q * 4 + 1) * 264 + tid] = v.y;
                xs[(q * 4 + 2) * 264 + tid] = v.z;
                xs[(q * 4 + 3) * 264 + tid] = v.w;
            }
        }
        __syncthreads();
#pragma unroll
        for (int kk = 0; kk < 20; kk++) {
            float4 xv = *(const float4*)&xs[kk * 264 + rg * 4];
            const u64* wp = (const u64*)&Ws[(kc * 20 + kk) * NH + cg * 8];
            u64 w0 = wp[0], w1 = wp[1], w2 = wp[2], w3 = wp[3];
            u64 xd0, xd1, xd2, xd3;
            asm("mov.b64 %0,{%1,%1};" : "=l"(xd0) : "r"(__float_as_uint(xv.x)));
            asm("mov.b64 %0,{%1,%1};" : "=l"(xd1) : "r"(__float_as_uint(xv.y)));
            asm("mov.b64 %0,{%1,%1};" : "=l"(xd2) : "r"(__float_as_uint(xv.z)));
            asm("mov.b64 %0,{%1,%1};" : "=l"(xd3) : "r"(__float_as_uint(xv.w)));
#define FMA2(a, b, c) asm("fma.rn.f32x2 %0,%1,%2,%0;" : "+l"(a) : "l"(b), "l"(c))
            FMA2(acc[0][0], xd0, w0); FMA2(acc[0][1], xd0, w1);
            FMA2(acc[0][2], xd0, w2); FMA2(acc[0][3], xd0, w3);
            FMA2(acc[1][0], xd1, w0); FMA2(acc[1][1], xd1, w1);
            FMA2(acc[1][2], xd1, w2); FMA2(acc[1][3], xd1, w3);
            FMA2(acc[2][0], xd2, w0); FMA2(acc[2][1], xd2, w1);
            FMA2(acc[2][2], xd2, w2); FMA2(acc[2][3], xd2, w3);
            FMA2(acc[3][0], xd3, w0); FMA2(acc[3][1], xd3, w1);
            FMA2(acc[3][2], xd3, w2); FMA2(acc[3][3], xd3, w3);
#undef FMA2
        }
    }

    // h' = h * dinv[row]  (dinv for in-block rows written in prologue)
#pragma unroll
    for (int ri = 0; ri < 4; ri++) {
        int gr = row0 + rg * 4 + ri;
        if (gr < N_NODES) {
            float di = g_dinv[gr];
            float2 p0 = *(float2*)&acc[ri][0];
            float2 p1 = *(float2*)&acc[ri][1];
            float2 p2 = *(float2*)&acc[ri][2];
            float2 p3 = *(float2*)&acc[ri][3];
            float* hp = g_h + (size_t)gr * NH + cg * 8;
            *(float4*)(hp)     = make_float4(p0.x * di, p0.y * di, p1.x * di, p1.y * di);
            *(float4*)(hp + 4) = make_float4(p2.x * di, p2.y * di, p3.x * di, p3.y * di);
        }
    }
}

// Scatter src into CSR slots, reading edge_index directly (L2-hot after k_deg).
__global__ __launch_bounds__(256) void k_fill(const unsigned* ei) {
    int is64 = detect_is64(ei);
    int e = blockIdx.x * 256 + threadIdx.x;
    if (e >= N_EDGES) return;
    int s, d;
    if (is64) {
        s = (int)((const long long*)ei)[e];
        d = (int)((const long long*)ei)[(long long)N_EDGES + e];
    } else {
        s = ((const int*)ei)[e];
        d = ((const int*)ei)[N_EDGES + e];
    }
    int slot = atomicAdd(&g_fillpos[d], 1);
    g_csr[slot] = s;
}

// Layer-1 aggregation: warp per node, 4 edges per iteration.
// Lane layout: grp = lane>>3 selects one of 4 edges, sub = lane&7 selects a
// float4 feature quad. h is premultiplied by dinv[src].
__global__ __launch_bounds__(512) void k_agg1(const float* __restrict__ b1,
                                              const float* __restrict__ W2) {
    int node = (blockIdx.x * 512 + threadIdx.x) >> 5;
    int lane = threadIdx.x & 31;
    if (node >= N_NODES) return;

    int off = g_off[node];
    int len = g_deg[node];
    float di = __ldg(&g_dinv[node]);
    int grp = lane >> 3;   // edge sub-slot 0..3
    int sub = lane & 7;    // feature quad 0..7

    float4 acc = make_float4(0.f, 0.f, 0.f, 0.f);
    for (int base = 0; base < len; base += 32) {
        int k = base + lane;
        int sl = (k < len) ? __ldg(&g_csr[off + k]) : 0;
        int cnt = min(32, len - base);
        for (int it = 0; it * 4 < cnt; it++) {
            int idx = it * 4 + grp;
            int s = __shfl_sync(0xffffffffu, sl, idx);
            if (idx < cnt) {
                float4 hv = __ldg((const float4*)(g_h + (size_t)s * NH) + sub);
                acc.x += hv.x; acc.y += hv.y; acc.z += hv.z; acc.w += hv.w;
            }
        }
    }
    // reduce the 4 edge-groups (lanes l, l+8, l+16, l+24)
#pragma unroll
    for (int o = 8; o <= 16; o <<= 1) {
        acc.x += __shfl_xor_sync(0xffffffffu, acc.x, o);
        acc.y += __shfl_xor_sync(0xffffffffu, acc.y, o);
        acc.z += __shfl_xor_sync(0xffffffffu, acc.z, o);
        acc.w += __shfl_xor_sync(0xffffffffu, acc.w, o);
    }
    // redistribute: feature c=lane lives in lane c>>2, component c&3
    float vx = __shfl_sync(0xffffffffu, acc.x, lane >> 2);
    float vy = __shfl_sync(0xffffffffu, acc.y, lane >> 2);
    float vz = __shfl_sync(0xffffffffu, acc.z, lane >> 2);
    float vw = __shfl_sync(0xffffffffu, acc.w, lane >> 2);
    int cm = lane & 3;
    float v = (cm == 0) ? vx : (cm == 1) ? vy : (cm == 2) ? vz : vw;

    // self loop, shared dinv[node] factor
    v += g_h[(size_t)node * NH + lane];
    v *= di;

    // bias + relu + dropout
    v += __ldg(&b1[lane]);
    v = fmaxf(v, 0.f);
    unsigned bits = rng_bits_partitionable((unsigned)(node * 32 + lane));
    v = ((bits >> 9) < 6710887u) ? v * 1.25f : 0.f;

    // @ W2, warp reduce; store g' = g * dinv[node]
    float p0 = v * __ldg(&W2[lane * 2 + 0]);
    float p1 = v * __ldg(&W2[lane * 2 + 1]);
#pragma unroll
    for (int o = 16; o; o >>= 1) {
        p0 += __shfl_xor_sync(0xffffffffu, p0, o);
        p1 += __shfl_xor_sync(0xffffffffu, p1, o);
    }
    if (lane == 0) {
        g_g[node * 2 + 0] = p0 * di;
        g_g[node * 2 + 1] = p1 * di;
    }
}

// Layer-2 aggregation (gather, warp per node) fused with b2 + log_softmax.
// Tail: reset g_deg / g_cursor to zero for the next graph replay.
__global__ __launch_bounds__(512) void k_agg2(const float* __restrict__ b2,
                                              float* __restrict__ out) {
    int node = (blockIdx.x * 512 + threadIdx.x) >> 5;
    int lane = threadIdx.x & 31;
    if (node >= N_NODES) return;

    int off = g_off[node];
    int len = g_deg[node];
    float di = __ldg(&g_dinv[node]);
    float a0 = 0.f, a1 = 0.f;
    for (int k = lane; k < len; k += 32) {
        int s = __ldg(&g_csr[off + k]);
        float2 gv = *(const float2*)(g_g + (size_t)s * 2);
        a0 += gv.x;
        a1 += gv.y;
    }
#pragma unroll
    for (int o = 16; o; o >>= 1) {
        a0 += __shfl_xor_sync(0xffffffffu, a0, o);
        a1 += __shfl_xor_sync(0xffffffffu, a1, o);
    }
    if (lane == 0) {
        float la = (a0 + g_g[node * 2 + 0]) * di + __ldg(&b2[0]);
        float lb = (a1 + g_g[node * 2 + 1]) * di + __ldg(&b2[1]);
        float m = fmaxf(la, lb);
        float lse = m + logf(expf(la - m) + expf(lb - m));
        *(float2*)(out + (size_t)node * 2) = make_float2(la - lse, lb - lse);
        g_deg[node] = 0;                       // reset for next replay
        if (node == 0) g_cursor = 0;
    }
}

// ---------------- launch ----------------
extern "C" void kernel_launch(void* const* d_in, const int* in_sizes, int n_in,
                              void* d_out, int out_size) {
    const float* x  = (const float*)d_in[0];
    const void*  ei = d_in[1];
    const float* W1 = (const float*)d_in[2];
    const float* b1 = (const float*)d_in[3];
    const float* W2 = (const float*)d_in[4];
    const float* b2 = (const float*)d_in[5];
    float* out = (float*)d_out;

    k_deg<<<(N_EDGES + 255) / 256, 256>>>((const unsigned*)ei);
    k_gemm1<<<(N_NODES + 255) / 256, 256>>>(x, W1);
    k_fill<<<(N_EDGES + 255) / 256, 256>>>((const unsigned*)ei);
    k_agg1<<<(int)(((long long)N_NODES * 32 + 511) / 512), 512>>>(b1, W2);
    k_agg2<<<(int)(((long long)N_NODES * 32 + 511) / 512), 512>>>(b2, out);
}